// round 8
// baseline (speedup 1.0000x reference)
#include <cuda_runtime.h>
#include <cuda_bf16.h>
#include <cstdint>

#define N_USER 100000
#define N_SPOT 100000
#define F_IN   64
#define HID    128
#define OUTC   64
#define EDG    500000
#define LEAK   0.2f
#define EPSF   1e-6f

// ---------------------------------------------------------------------------
// Scratch (device globals; no allocation allowed)
// ---------------------------------------------------------------------------
__device__ float g_srcA[(size_t)N_USER * HID];
__device__ float g_tgtA[(size_t)N_SPOT * HID];
__device__ float g_srcB[(size_t)N_SPOT * HID];
__device__ float g_tgtB[(size_t)N_USER * HID];
__device__ float g_hu[(size_t)N_USER * HID];     // tf32-rounded hidden
__device__ float g_hs[(size_t)N_SPOT * HID];
__device__ float g_x32a[(size_t)N_USER * HID];   // preconverted X scratch
__device__ float g_x32b[(size_t)N_SPOT * HID];

__device__ float g_alsA[N_USER];
__device__ float g_altA[N_SPOT];
__device__ float g_alsB[N_SPOT];
__device__ float g_altB[N_USER];

__device__ int g_si2_us[EDG];
__device__ int g_si2_su[EDG];
__device__ int g_cnt_us[N_SPOT + 1];
__device__ int g_off_us[N_SPOT + 1];
__device__ int g_cur_us[N_SPOT + 1];
__device__ int g_cnt_su[N_USER + 1];
__device__ int g_off_su[N_USER + 1];
__device__ int g_cur_su[N_USER + 1];
__device__ int g_csr_us[EDG];
__device__ int g_csr_su[EDG];
__device__ int g_row_us[EDG];
__device__ int g_row_su[EDG];
__device__ float g_att[EDG];

__device__ __forceinline__ float f2tf32(float x) {
    float y;
    asm("cvt.rna.tf32.f32 %0, %1;" : "=f"(y) : "f"(x));
    return y;
}
__device__ __forceinline__ uint32_t smem_u32(const void* p) {
    uint32_t a;
    asm("{ .reg .u64 t; cvta.to.shared.u64 t, %1; cvt.u32.u64 %0, t; }" : "=r"(a) : "l"(p));
    return a;
}
__device__ __forceinline__ void cp_async16(void* dst, const void* src) {
    asm volatile("cp.async.ca.shared.global [%0], [%1], 16;"
                 :: "r"(smem_u32(dst)), "l"(src) : "memory");
}
__device__ __forceinline__ void cp_commit() {
    asm volatile("cp.async.commit_group;" ::: "memory");
}
template <int NG>
__device__ __forceinline__ void cp_wait() {
    asm volatile("cp.async.wait_group %0;" :: "n"(NG) : "memory");
}

// ---------------------------------------------------------------------------
// Elementwise tf32 pre-convert
// ---------------------------------------------------------------------------
__global__ void k_cvt(const float4* __restrict__ in, float4* __restrict__ out, int n4) {
    int i = blockIdx.x * blockDim.x + threadIdx.x;
    if (i < n4) {
        float4 v = in[i];
        v.x = f2tf32(v.x); v.y = f2tf32(v.y); v.z = f2tf32(v.z); v.w = f2tf32(v.w);
        out[i] = v;
    }
}

// ---------------------------------------------------------------------------
// Edge prep kernels
// ---------------------------------------------------------------------------
__global__ void k_gather2(const int* __restrict__ si, int* __restrict__ s2, int E) {
    int e = blockIdx.x * blockDim.x + threadIdx.x;
    if (e < E) {
        int a = si[e];
        s2[e] = si[a];
    }
}

__global__ void k_hist(const int* __restrict__ ti, int* __restrict__ cnt, int E) {
    int e = blockIdx.x * blockDim.x + threadIdx.x;
    if (e < E) atomicAdd(&cnt[ti[e]], 1);
}

__global__ void k_scan(const int* __restrict__ cnt, int* __restrict__ off,
                       int* __restrict__ cur, int n) {
    __shared__ int s[1024];
    int tid = threadIdx.x;
    int chunk = (n + 1023) / 1024;
    int beg = tid * chunk;
    int end = beg + chunk; if (end > n) end = n; if (beg > n) beg = n;
    int sum = 0;
    for (int i = beg; i < end; i++) sum += cnt[i];
    s[tid] = sum;
    __syncthreads();
    for (int d = 1; d < 1024; d <<= 1) {
        int v = 0;
        if (tid >= d) v = s[tid - d];
        __syncthreads();
        s[tid] += v;
        __syncthreads();
    }
    int run = s[tid] - sum;
    for (int i = beg; i < end; i++) {
        off[i] = run; cur[i] = run;
        run += cnt[i];
    }
    if (tid == 1023) off[n] = s[1023];
}

__global__ void k_scatter(const int* __restrict__ ti, const int* __restrict__ s2,
                          int* __restrict__ cur, int* __restrict__ csr,
                          int* __restrict__ rowOf, int E) {
    int e = blockIdx.x * blockDim.x + threadIdx.x;
    if (e < E) {
        int t = ti[e];
        int p = atomicAdd(&cur[t], 1);
        csr[p] = s2[e];
        rowOf[p] = t;
    }
}

__global__ void k_att(const int* __restrict__ csr, const int* __restrict__ rowOf,
                      const float* __restrict__ alpha_s, const float* __restrict__ alpha_t,
                      float* __restrict__ att, int E) {
    int j = blockIdx.x * blockDim.x + threadIdx.x;
    if (j < E) {
        float l = alpha_s[csr[j]] + alpha_t[rowOf[j]];
        l = (l > 0.f) ? l : LEAK * l;
        att[j] = __expf(l);
    }
}

// ---------------------------------------------------------------------------
// Persistent tf32 mma.sync GEMM, cp.async double-buffered A, W resident.
// X must be tf32-pre-rounded. 256 threads = 8 warps (2M x 4N), BM=64.
//   N=256 dual-output + dual fused alpha; N=64 single + bias.
// ---------------------------------------------------------------------------
template <int K, int N, bool ALPHA, bool BIAS>
__global__ __launch_bounds__(256, 2)
void k_gemm_tc(const float* __restrict__ X,
               const float* __restrict__ W0, const float* __restrict__ W1,
               const float* __restrict__ av0, const float* __restrict__ av1,
               const float* __restrict__ bias,
               float* __restrict__ Y0, float* __restrict__ Y1,
               float* __restrict__ al0, float* __restrict__ al1, int M) {
    constexpr int BM = 64;
    constexpr int KP = K + 4;
    constexpr int NP = N + 8;
    constexpr int WN = N / 4;
    constexpr int NT = WN / 8;
    constexpr int XF = BM * K / 1024;     // float4/thread per tile
    extern __shared__ float smf[];
    float* Wsm = smf;                     // [K][NP]
    float* A0  = smf + K * NP;            // [BM][KP] x2
    float* A1  = A0 + BM * KP;
    float* red = A1 + BM * KP;            // [BM][5]

    const int tid = threadIdx.x;
    const int wid = tid >> 5;
    const int lane = tid & 31;
    const int warpM = wid >> 2;
    const int warpN = wid & 3;
    const int q = lane >> 2;
    const int t = lane & 3;

    // ---- stage W once (k-major, cvt) ----
    for (int i = tid; i < K * N / 4; i += 256) {
        int k = i / (N / 4);
        int n4 = (i % (N / 4)) * 4;
        const float* src = (N == 256)
            ? ((n4 < 128) ? (W0 + (size_t)k * 128 + n4) : (W1 + (size_t)k * 128 + (n4 - 128)))
            : (W0 + (size_t)k * N + n4);
        float4 v = *(const float4*)src;
        v.x = f2tf32(v.x); v.y = f2tf32(v.y); v.z = f2tf32(v.z); v.w = f2tf32(v.w);
        *(float4*)(Wsm + k * NP + n4) = v;
    }

    const int ntiles = (M + BM - 1) / BM;

    // prologue: async-load first tile
    if ((int)blockIdx.x < ntiles) {
#pragma unroll
        for (int f = 0; f < XF; f++) {
            int i = tid + f * 256;
            int r = i / (K / 4);
            int c4 = (i % (K / 4)) * 4;
            int gr = blockIdx.x * BM + r;
            if (gr >= M) gr = M - 1;
            cp_async16(A0 + r * KP + c4, X + (size_t)gr * K + c4);
        }
    }
    cp_commit();

    int it = 0;
    for (int tile = blockIdx.x; tile < ntiles; tile += gridDim.x, it++) {
        float* curA = (it & 1) ? A1 : A0;
        float* nxtA = (it & 1) ? A0 : A1;

        int next = tile + gridDim.x;
        if (next < ntiles) {
#pragma unroll
            for (int f = 0; f < XF; f++) {
                int i = tid + f * 256;
                int r = i / (K / 4);
                int c4 = (i % (K / 4)) * 4;
                int gr = next * BM + r;
                if (gr >= M) gr = M - 1;
                cp_async16(nxtA + r * KP + c4, X + (size_t)gr * K + c4);
            }
        }
        cp_commit();
        cp_wait<1>();        // current tile's data landed
        __syncthreads();     // also orders W staging on first iter

        float acc[2][NT][4];
#pragma unroll
        for (int mt = 0; mt < 2; mt++)
#pragma unroll
            for (int nt = 0; nt < NT; nt++)
#pragma unroll
                for (int j = 0; j < 4; j++) acc[mt][nt][j] = 0.f;

        const uint32_t* Au = (const uint32_t*)curA;
        const uint32_t* Bu = (const uint32_t*)Wsm;

#pragma unroll
        for (int kk = 0; kk < K; kk += 8) {
            uint32_t a[2][4];
#pragma unroll
            for (int mt = 0; mt < 2; mt++) {
                int r0 = warpM * 32 + mt * 16 + q;
                a[mt][0] = Au[r0 * KP + kk + t];
                a[mt][1] = Au[(r0 + 8) * KP + kk + t];
                a[mt][2] = Au[r0 * KP + kk + 4 + t];
                a[mt][3] = Au[(r0 + 8) * KP + kk + 4 + t];
            }
            uint32_t b[NT][2];
#pragma unroll
            for (int nt = 0; nt < NT; nt++) {
                int nc = warpN * WN + nt * 8 + q;
                b[nt][0] = Bu[(kk + t) * NP + nc];
                b[nt][1] = Bu[(kk + 4 + t) * NP + nc];
            }
#pragma unroll
            for (int mt = 0; mt < 2; mt++)
#pragma unroll
                for (int nt = 0; nt < NT; nt++) {
                    asm("mma.sync.aligned.m16n8k8.row.col.f32.tf32.tf32.f32 "
                        "{%0,%1,%2,%3}, {%4,%5,%6,%7}, {%8,%9}, {%0,%1,%2,%3};"
                        : "+f"(acc[mt][nt][0]), "+f"(acc[mt][nt][1]),
                          "+f"(acc[mt][nt][2]), "+f"(acc[mt][nt][3])
                        : "r"(a[mt][0]), "r"(a[mt][1]), "r"(a[mt][2]), "r"(a[mt][3]),
                          "r"(b[nt][0]), "r"(b[nt][1]));
                }
        }

        const int rowBase = tile * BM;
#pragma unroll
        for (int mt = 0; mt < 2; mt++) {
            int lr0 = warpM * 32 + mt * 16 + q;
            int r0 = rowBase + lr0;
            float p0 = 0.f, p1 = 0.f;
#pragma unroll
            for (int nt = 0; nt < NT; nt++) {
                int cb = warpN * WN + nt * 8 + t * 2;
                float v0 = acc[mt][nt][0], v1 = acc[mt][nt][1];
                float v2 = acc[mt][nt][2], v3 = acc[mt][nt][3];
                if (BIAS) {
                    v0 += bias[cb]; v1 += bias[cb + 1];
                    v2 += bias[cb]; v3 += bias[cb + 1];
                }
                float* Yt;
                const float* avt;
                int cc;
                if (N == 256) {
                    bool hi = cb >= 128;
                    Yt = hi ? Y1 : Y0;
                    avt = hi ? av1 : av0;
                    cc = cb & 127;
                } else {
                    Yt = Y0; avt = av0; cc = cb;
                }
                constexpr int YSTR = (N == 256) ? 128 : N;
                if (r0 < M) *(float2*)(Yt + (size_t)r0 * YSTR + cc) = make_float2(v0, v1);
                if (r0 + 8 < M) *(float2*)(Yt + (size_t)(r0 + 8) * YSTR + cc) = make_float2(v2, v3);
                if (ALPHA) {
                    float a0 = avt[cc], a1 = avt[cc + 1];
                    p0 += v0 * a0 + v1 * a1;
                    p1 += v2 * a0 + v3 * a1;
                }
            }
            if (ALPHA) {
                p0 += __shfl_xor_sync(0xffffffffu, p0, 1);
                p0 += __shfl_xor_sync(0xffffffffu, p0, 2);
                p1 += __shfl_xor_sync(0xffffffffu, p1, 1);
                p1 += __shfl_xor_sync(0xffffffffu, p1, 2);
                if (t == 0) {
                    red[lr0 * 5 + warpN] = p0;
                    red[(lr0 + 8) * 5 + warpN] = p1;
                }
            }
        }
        __syncthreads();   // curA reads + red writes complete
        if (ALPHA) {
            if (tid < BM) {
                int gr = rowBase + tid;
                if (gr < M) {
                    al0[gr] = red[tid * 5 + 0] + red[tid * 5 + 1];
                    al1[gr] = red[tid * 5 + 2] + red[tid * 5 + 3];
                }
            }
            __syncthreads();  // red reads complete before next tile overwrites
        }
    }
}

// ---------------------------------------------------------------------------
// Aggregation: one warp per target node; predicated always-4 loop.
// ROUND: tf32-round the output (for hidden layers feeding the next GEMM).
// ---------------------------------------------------------------------------
template <bool ROUND>
__global__ __launch_bounds__(256)
void k_agg(const float4* __restrict__ tgt, const float4* __restrict__ src,
           const float* __restrict__ att,
           const int* __restrict__ off, const int* __restrict__ csr,
           float4* __restrict__ out, int n) {
    int w = (blockIdx.x * blockDim.x + threadIdx.x) >> 5;
    int lid = threadIdx.x & 31;
    if (w >= n) return;
    int beg = off[w];
    int end = off[w + 1];
    float4 acc = make_float4(0.f, 0.f, 0.f, 0.f);
    float den = 0.f;
    int e1 = end - 1;
    for (int j = beg; j < end; j += 4) {
        int i1 = j + 1 <= e1 ? j + 1 : e1;
        int i2 = j + 2 <= e1 ? j + 2 : e1;
        int i3 = j + 3 <= e1 ? j + 3 : e1;
        int s0 = csr[j], s1 = csr[i1], s2 = csr[i2], s3 = csr[i3];
        float a0 = att[j];
        float a1 = (j + 1 < end) ? att[i1] : 0.f;
        float a2 = (j + 2 < end) ? att[i2] : 0.f;
        float a3 = (j + 3 < end) ? att[i3] : 0.f;
        float4 v0 = src[(size_t)s0 * 32 + lid];
        float4 v1 = src[(size_t)s1 * 32 + lid];
        float4 v2 = src[(size_t)s2 * 32 + lid];
        float4 v3 = src[(size_t)s3 * 32 + lid];
        den += (a0 + a1) + (a2 + a3);
        acc.x += a0 * v0.x + a1 * v1.x + a2 * v2.x + a3 * v3.x;
        acc.y += a0 * v0.y + a1 * v1.y + a2 * v2.y + a3 * v3.y;
        acc.z += a0 * v0.z + a1 * v1.z + a2 * v2.z + a3 * v3.z;
        acc.w += a0 * v0.w + a1 * v1.w + a2 * v2.w + a3 * v3.w;
    }
    float inv = 1.0f / (den + EPSF);
    float4 tv = tgt[(size_t)w * 32 + lid];
    float4 r;
    r.x = fmaxf(tv.x + acc.x * inv, 0.f);
    r.y = fmaxf(tv.y + acc.y * inv, 0.f);
    r.z = fmaxf(tv.z + acc.z * inv, 0.f);
    r.w = fmaxf(tv.w + acc.w * inv, 0.f);
    if (ROUND) {
        r.x = f2tf32(r.x); r.y = f2tf32(r.y);
        r.z = f2tf32(r.z); r.w = f2tf32(r.w);
    }
    out[(size_t)w * 32 + lid] = r;
}

// ---------------------------------------------------------------------------
// Host launcher
// ---------------------------------------------------------------------------
static inline float* symf(const void* sym) {
    void* p = nullptr;
    cudaGetSymbolAddress(&p, sym);
    return (float*)p;
}
static inline int* symi(const void* sym) {
    void* p = nullptr;
    cudaGetSymbolAddress(&p, sym);
    return (int*)p;
}

extern "C" void kernel_launch(void* const* d_in, const int* in_sizes, int n_in,
                              void* d_out, int out_size) {
    const float* x_user = (const float*)d_in[0];
    const float* x_spot = (const float*)d_in[1];
    const int*   e_us   = (const int*)d_in[2];
    const int*   e_su   = (const int*)d_in[3];
    const float* Ws_us0 = (const float*)d_in[4];
    const float* Wt_us0 = (const float*)d_in[5];
    const float* a_us0  = (const float*)d_in[6];
    const float* Ws_su0 = (const float*)d_in[7];
    const float* Wt_su0 = (const float*)d_in[8];
    const float* a_su0  = (const float*)d_in[9];
    const float* Ws_us1 = (const float*)d_in[10];
    const float* Wt_us1 = (const float*)d_in[11];
    const float* a_us1  = (const float*)d_in[12];
    const float* Ws_su1 = (const float*)d_in[13];
    const float* Wt_su1 = (const float*)d_in[14];
    const float* a_su1  = (const float*)d_in[15];
    const float* W_ou   = (const float*)d_in[16];
    const float* b_ou   = (const float*)d_in[17];
    const float* W_os   = (const float*)d_in[18];
    const float* b_os   = (const float*)d_in[19];

    float* out = (float*)d_out;
    float* xu_out = out;
    float* xs_out = out + (size_t)N_USER * HID;
    float* ou_out = xs_out + (size_t)N_SPOT * HID;
    float* os_out = ou_out + (size_t)N_USER * OUTC;

    float* srcA = symf(g_srcA); float* tgtA = symf(g_tgtA);
    float* srcB = symf(g_srcB); float* tgtB = symf(g_tgtB);
    float* hu = symf(g_hu);     float* hs = symf(g_hs);
    float* x32a = symf(g_x32a); float* x32b = symf(g_x32b);
    float* alsA = symf(g_alsA); float* altA = symf(g_altA);
    float* alsB = symf(g_alsB); float* altB = symf(g_altB);
    int* si2_us = symi(g_si2_us); int* si2_su = symi(g_si2_su);
    int* cnt_us = symi(g_cnt_us); int* off_us = symi(g_off_us); int* cur_us = symi(g_cur_us);
    int* cnt_su = symi(g_cnt_su); int* off_su = symi(g_off_su); int* cur_su = symi(g_cur_su);
    int* csr_us = symi(g_csr_us); int* csr_su = symi(g_csr_su);
    int* row_us = symi(g_row_us); int* row_su = symi(g_row_su);
    float* attb = symf(g_att);

    const int EB = (EDG + 255) / 256;
    const int GP = 296;
    const int GP1 = 148;
    const int AU = (N_USER * 32 + 255) / 256;
    const int AS = (N_SPOT * 32 + 255) / 256;
    const int C64 = (N_USER * F_IN / 4 + 255) / 256;
    const int C128 = (N_USER * HID / 4 + 255) / 256;

    const int SM_L0 = (64 * (256 + 8) + 2 * 64 * (64 + 4) + 64 * 5) * 4;     // ~104 KB
    const int SM_L1 = (128 * (256 + 8) + 2 * 64 * (128 + 4) + 64 * 5) * 4;   // ~204 KB
    const int SM_FN = (128 * (64 + 8) + 2 * 64 * (128 + 4) + 64 * 5) * 4;    // ~106 KB

    cudaFuncSetAttribute((const void*)k_gemm_tc<64, 256, true, false>,
                         cudaFuncAttributeMaxDynamicSharedMemorySize, SM_L0);
    cudaFuncSetAttribute((const void*)k_gemm_tc<128, 256, true, false>,
                         cudaFuncAttributeMaxDynamicSharedMemorySize, SM_L1);
    cudaFuncSetAttribute((const void*)k_gemm_tc<128, 64, false, true>,
                         cudaFuncAttributeMaxDynamicSharedMemorySize, SM_FN);

    // ---- prep + preconvert; launch #5 = fused L0 GEMM (profiled) ----
    k_cvt<<<C64, 256>>>((const float4*)x_user, (float4*)x32a, N_USER * F_IN / 4);   // 0
    k_cvt<<<C64, 256>>>((const float4*)x_spot, (float4*)x32b, N_SPOT * F_IN / 4);   // 1
    k_gather2<<<EB, 256>>>(e_us, si2_us, EDG);                                      // 2
    k_gather2<<<EB, 256>>>(e_su, si2_su, EDG);                                      // 3
    cudaMemsetAsync(cnt_us, 0, sizeof(int) * (N_SPOT + 1));                         // 4
    // x_user -> [srcA | tgtB], alphas [alsA | altB]
    k_gemm_tc<64, 256, true, false><<<GP, 256, SM_L0>>>(                            // 5
        x32a, Ws_us0, Wt_su0, a_us0, a_su0 + HID, nullptr,
        srcA, tgtB, alsA, altB, N_USER);
    cudaMemsetAsync(cnt_su, 0, sizeof(int) * (N_USER + 1));
    k_hist<<<EB, 256>>>(e_us + EDG, cnt_us, EDG);
    k_hist<<<EB, 256>>>(e_su + EDG, cnt_su, EDG);
    k_scan<<<1, 1024>>>(cnt_us, off_us, cur_us, N_SPOT);
    k_scan<<<1, 1024>>>(cnt_su, off_su, cur_su, N_USER);
    k_scatter<<<EB, 256>>>(e_us + EDG, si2_us, cur_us, csr_us, row_us, EDG);
    k_scatter<<<EB, 256>>>(e_su + EDG, si2_su, cur_su, csr_su, row_su, EDG);
    // x_spot -> [srcB | tgtA], alphas [alsB | altA]
    k_gemm_tc<64, 256, true, false><<<GP, 256, SM_L0>>>(
        x32b, Ws_su0, Wt_us0, a_su0, a_us0 + HID, nullptr,
        srcB, tgtA, alsB, altA, N_SPOT);

    // ---- layer 0 aggregation (outputs tf32-rounded; feed L1 GEMMs only) ----
    k_att<<<EB, 256>>>(csr_us, row_us, alsA, altA, attb, EDG);
    k_agg<true><<<AS, 256>>>((const float4*)tgtA, (const float4*)srcA, attb,
                             off_us, csr_us, (float4*)hs, N_SPOT);
    k_att<<<EB, 256>>>(csr_su, row_su, alsB, altB, attb, EDG);
    k_agg<true><<<AU, 256>>>((const float4*)tgtB, (const float4*)srcB, attb,
                             off_su, csr_su, (float4*)hu, N_USER);

    // ---- layer 1 (K=128, fused) ----
    k_gemm_tc<128, 256, true, false><<<GP1, 256, SM_L1>>>(
        hu, Ws_us1, Wt_su1, a_us1, a_su1 + HID, nullptr,
        srcA, tgtB, alsA, altB, N_USER);
    k_gemm_tc<128, 256, true, false><<<GP1, 256, SM_L1>>>(
        hs, Ws_su1, Wt_us1, a_su1, a_us1 + HID, nullptr,
        srcB, tgtA, alsB, altA, N_SPOT);
    k_att<<<EB, 256>>>(csr_us, row_us, alsA, altA, attb, EDG);
    k_agg<false><<<AS, 256>>>((const float4*)tgtA, (const float4*)srcA, attb,
                              off_us, csr_us, (float4*)xs_out, N_SPOT);
    k_att<<<EB, 256>>>(csr_su, row_su, alsB, altB, attb, EDG);
    k_agg<false><<<AU, 256>>>((const float4*)tgtB, (const float4*)srcB, attb,
                              off_su, csr_su, (float4*)xu_out, N_USER);

    // ---- final per-type linear (pre-convert exact outputs, then GEMM) ----
    k_cvt<<<C128, 256>>>((const float4*)xu_out, (float4*)x32a, N_USER * HID / 4);
    k_cvt<<<C128, 256>>>((const float4*)xs_out, (float4*)x32b, N_SPOT * HID / 4);
    k_gemm_tc<128, 64, false, true><<<GP, 256, SM_FN>>>(
        x32a, W_ou, nullptr, nullptr, nullptr, b_ou,
        ou_out, nullptr, nullptr, nullptr, N_USER);
    k_gemm_tc<128, 64, false, true><<<GP, 256, SM_FN>>>(
        x32b, W_os, nullptr, nullptr, nullptr, b_os,
        os_out, nullptr, nullptr, nullptr, N_SPOT);
}

// round 9
// speedup vs baseline: 1.0513x; 1.0513x over previous
#include <cuda_runtime.h>
#include <cuda_bf16.h>
#include <cstdint>

#define N_USER 100000
#define N_SPOT 100000
#define F_IN   64
#define HID    128
#define OUTC   64
#define EDG    500000
#define LEAK   0.2f
#define EPSF   1e-6f

// ---------------------------------------------------------------------------
// Scratch (device globals; no allocation allowed)
// ---------------------------------------------------------------------------
__device__ float g_srcA[(size_t)N_USER * HID];
__device__ float g_tgtA[(size_t)N_SPOT * HID];
__device__ float g_srcB[(size_t)N_SPOT * HID];
__device__ float g_tgtB[(size_t)N_USER * HID];
__device__ float g_hu[(size_t)N_USER * HID];
__device__ float g_hs[(size_t)N_SPOT * HID];

__device__ float g_alsA[N_USER];
__device__ float g_altA[N_SPOT];
__device__ float g_alsB[N_SPOT];
__device__ float g_altB[N_USER];

__device__ int g_si2_us[EDG];
__device__ int g_si2_su[EDG];
__device__ int g_cnt_us[N_SPOT + 1];
__device__ int g_off_us[N_SPOT + 1];
__device__ int g_cur_us[N_SPOT + 1];
__device__ int g_cnt_su[N_USER + 1];
__device__ int g_off_su[N_USER + 1];
__device__ int g_cur_su[N_USER + 1];
__device__ int g_csr_us[EDG];
__device__ int g_csr_su[EDG];
__device__ int g_row_us[EDG];
__device__ int g_row_su[EDG];
__device__ float g_att[EDG];

__device__ __forceinline__ float f2tf32(float x) {
    float y;
    asm("cvt.rna.tf32.f32 %0, %1;" : "=f"(y) : "f"(x));
    return y;
}
__device__ __forceinline__ uint32_t smem_u32(const void* p) {
    uint32_t a;
    asm("{ .reg .u64 t; cvta.to.shared.u64 t, %1; cvt.u32.u64 %0, t; }" : "=r"(a) : "l"(p));
    return a;
}
__device__ __forceinline__ void cp_async16(void* dst, const void* src) {
    asm volatile("cp.async.ca.shared.global [%0], [%1], 16;"
                 :: "r"(smem_u32(dst)), "l"(src) : "memory");
}
__device__ __forceinline__ void cp_commit() {
    asm volatile("cp.async.commit_group;" ::: "memory");
}
template <int NG>
__device__ __forceinline__ void cp_wait() {
    asm volatile("cp.async.wait_group %0;" :: "n"(NG) : "memory");
}

// ---------------------------------------------------------------------------
// Edge prep kernels
// ---------------------------------------------------------------------------
__global__ void k_gather2(const int* __restrict__ si, int* __restrict__ s2, int E) {
    int e = blockIdx.x * blockDim.x + threadIdx.x;
    if (e < E) {
        int a = si[e];
        s2[e] = si[a];
    }
}

__global__ void k_hist(const int* __restrict__ ti, int* __restrict__ cnt, int E) {
    int e = blockIdx.x * blockDim.x + threadIdx.x;
    if (e < E) atomicAdd(&cnt[ti[e]], 1);
}

__global__ void k_scan(const int* __restrict__ cnt, int* __restrict__ off,
                       int* __restrict__ cur, int n) {
    __shared__ int s[1024];
    int tid = threadIdx.x;
    int chunk = (n + 1023) / 1024;
    int beg = tid * chunk;
    int end = beg + chunk; if (end > n) end = n; if (beg > n) beg = n;
    int sum = 0;
    for (int i = beg; i < end; i++) sum += cnt[i];
    s[tid] = sum;
    __syncthreads();
    for (int d = 1; d < 1024; d <<= 1) {
        int v = 0;
        if (tid >= d) v = s[tid - d];
        __syncthreads();
        s[tid] += v;
        __syncthreads();
    }
    int run = s[tid] - sum;
    for (int i = beg; i < end; i++) {
        off[i] = run; cur[i] = run;
        run += cnt[i];
    }
    if (tid == 1023) off[n] = s[1023];
}

__global__ void k_scatter(const int* __restrict__ ti, const int* __restrict__ s2,
                          int* __restrict__ cur, int* __restrict__ csr,
                          int* __restrict__ rowOf, int E) {
    int e = blockIdx.x * blockDim.x + threadIdx.x;
    if (e < E) {
        int t = ti[e];
        int p = atomicAdd(&cur[t], 1);
        csr[p] = s2[e];
        rowOf[p] = t;
    }
}

__global__ void k_att(const int* __restrict__ csr, const int* __restrict__ rowOf,
                      const float* __restrict__ alpha_s, const float* __restrict__ alpha_t,
                      float* __restrict__ att, int E) {
    int j = blockIdx.x * blockDim.x + threadIdx.x;
    if (j < E) {
        float l = alpha_s[csr[j]] + alpha_t[rowOf[j]];
        l = (l > 0.f) ? l : LEAK * l;
        att[j] = __expf(l);
    }
}

// ---------------------------------------------------------------------------
// Shared GEMM epilogue macro-body is duplicated in both kernels below.
// k_gemm_db: persistent, cp.async double-buffered A (in-smem tf32 convert),
//            W resident. 2 CTAs/SM. Used for L0 (K=64,N=256) and FN (128,64).
// ---------------------------------------------------------------------------
template <int K, int N, bool ALPHA, bool BIAS>
__global__ __launch_bounds__(256, 2)
void k_gemm_db(const float* __restrict__ X,
               const float* __restrict__ W0, const float* __restrict__ W1,
               const float* __restrict__ av0, const float* __restrict__ av1,
               const float* __restrict__ bias,
               float* __restrict__ Y0, float* __restrict__ Y1,
               float* __restrict__ al0, float* __restrict__ al1, int M) {
    constexpr int BM = 64;
    constexpr int KP = K + 4;
    constexpr int NP = N + 8;
    constexpr int WN = N / 4;
    constexpr int NT = WN / 8;
    constexpr int XF = BM * K / 1024;
    extern __shared__ float smf[];
    float* Wsm = smf;                     // [K][NP]
    float* A0  = smf + K * NP;            // [BM][KP] x2
    float* A1  = A0 + BM * KP;
    float* red = A1 + BM * KP;            // [BM][5]

    const int tid = threadIdx.x;
    const int wid = tid >> 5;
    const int lane = tid & 31;
    const int warpM = wid >> 2;
    const int warpN = wid & 3;
    const int q = lane >> 2;
    const int t = lane & 3;

    // ---- stage W once (k-major, cvt) ----
    for (int i = tid; i < K * N / 4; i += 256) {
        int k = i / (N / 4);
        int n4 = (i % (N / 4)) * 4;
        const float* src = (N == 256)
            ? ((n4 < 128) ? (W0 + (size_t)k * 128 + n4) : (W1 + (size_t)k * 128 + (n4 - 128)))
            : (W0 + (size_t)k * N + n4);
        float4 v = *(const float4*)src;
        v.x = f2tf32(v.x); v.y = f2tf32(v.y); v.z = f2tf32(v.z); v.w = f2tf32(v.w);
        *(float4*)(Wsm + k * NP + n4) = v;
    }

    const int ntiles = (M + BM - 1) / BM;

    if ((int)blockIdx.x < ntiles) {
#pragma unroll
        for (int f = 0; f < XF; f++) {
            int i = tid + f * 256;
            int r = i / (K / 4);
            int c4 = (i % (K / 4)) * 4;
            int gr = blockIdx.x * BM + r;
            if (gr >= M) gr = M - 1;
            cp_async16(A0 + r * KP + c4, X + (size_t)gr * K + c4);
        }
    }
    cp_commit();

    int it = 0;
    for (int tile = blockIdx.x; tile < ntiles; tile += gridDim.x, it++) {
        float* curA = (it & 1) ? A1 : A0;
        float* nxtA = (it & 1) ? A0 : A1;

        int next = tile + gridDim.x;
        if (next < ntiles) {
#pragma unroll
            for (int f = 0; f < XF; f++) {
                int i = tid + f * 256;
                int r = i / (K / 4);
                int c4 = (i % (K / 4)) * 4;
                int gr = next * BM + r;
                if (gr >= M) gr = M - 1;
                cp_async16(nxtA + r * KP + c4, X + (size_t)gr * K + c4);
            }
        }
        cp_commit();
        cp_wait<1>();        // current tile landed
        // in-place tf32 convert (same thread -> same addresses it copied)
#pragma unroll
        for (int f = 0; f < XF; f++) {
            int i = tid + f * 256;
            int r = i / (K / 4);
            int c4 = (i % (K / 4)) * 4;
            float4 v = *(const float4*)(curA + r * KP + c4);
            v.x = f2tf32(v.x); v.y = f2tf32(v.y); v.z = f2tf32(v.z); v.w = f2tf32(v.w);
            *(float4*)(curA + r * KP + c4) = v;
        }
        __syncthreads();     // convert done + W ready (first iter)

        float acc[2][NT][4];
#pragma unroll
        for (int mt = 0; mt < 2; mt++)
#pragma unroll
            for (int nt = 0; nt < NT; nt++)
#pragma unroll
                for (int j = 0; j < 4; j++) acc[mt][nt][j] = 0.f;

        const uint32_t* Au = (const uint32_t*)curA;
        const uint32_t* Bu = (const uint32_t*)Wsm;

#pragma unroll
        for (int kk = 0; kk < K; kk += 8) {
            uint32_t a[2][4];
#pragma unroll
            for (int mt = 0; mt < 2; mt++) {
                int r0 = warpM * 32 + mt * 16 + q;
                a[mt][0] = Au[r0 * KP + kk + t];
                a[mt][1] = Au[(r0 + 8) * KP + kk + t];
                a[mt][2] = Au[r0 * KP + kk + 4 + t];
                a[mt][3] = Au[(r0 + 8) * KP + kk + 4 + t];
            }
            uint32_t b[NT][2];
#pragma unroll
            for (int nt = 0; nt < NT; nt++) {
                int nc = warpN * WN + nt * 8 + q;
                b[nt][0] = Bu[(kk + t) * NP + nc];
                b[nt][1] = Bu[(kk + 4 + t) * NP + nc];
            }
#pragma unroll
            for (int mt = 0; mt < 2; mt++)
#pragma unroll
                for (int nt = 0; nt < NT; nt++) {
                    asm("mma.sync.aligned.m16n8k8.row.col.f32.tf32.tf32.f32 "
                        "{%0,%1,%2,%3}, {%4,%5,%6,%7}, {%8,%9}, {%0,%1,%2,%3};"
                        : "+f"(acc[mt][nt][0]), "+f"(acc[mt][nt][1]),
                          "+f"(acc[mt][nt][2]), "+f"(acc[mt][nt][3])
                        : "r"(a[mt][0]), "r"(a[mt][1]), "r"(a[mt][2]), "r"(a[mt][3]),
                          "r"(b[nt][0]), "r"(b[nt][1]));
                }
        }

        const int rowBase = tile * BM;
#pragma unroll
        for (int mt = 0; mt < 2; mt++) {
            int lr0 = warpM * 32 + mt * 16 + q;
            int r0 = rowBase + lr0;
            float p0 = 0.f, p1 = 0.f;
#pragma unroll
            for (int nt = 0; nt < NT; nt++) {
                int cb = warpN * WN + nt * 8 + t * 2;
                float v0 = acc[mt][nt][0], v1 = acc[mt][nt][1];
                float v2 = acc[mt][nt][2], v3 = acc[mt][nt][3];
                if (BIAS) {
                    v0 += bias[cb]; v1 += bias[cb + 1];
                    v2 += bias[cb]; v3 += bias[cb + 1];
                }
                float* Yt;
                const float* avt;
                int cc;
                if (N == 256) {
                    bool hi = cb >= 128;
                    Yt = hi ? Y1 : Y0;
                    avt = hi ? av1 : av0;
                    cc = cb & 127;
                } else {
                    Yt = Y0; avt = av0; cc = cb;
                }
                constexpr int YSTR = (N == 256) ? 128 : N;
                if (r0 < M) *(float2*)(Yt + (size_t)r0 * YSTR + cc) = make_float2(v0, v1);
                if (r0 + 8 < M) *(float2*)(Yt + (size_t)(r0 + 8) * YSTR + cc) = make_float2(v2, v3);
                if (ALPHA) {
                    float a0 = avt[cc], a1 = avt[cc + 1];
                    p0 += v0 * a0 + v1 * a1;
                    p1 += v2 * a0 + v3 * a1;
                }
            }
            if (ALPHA) {
                p0 += __shfl_xor_sync(0xffffffffu, p0, 1);
                p0 += __shfl_xor_sync(0xffffffffu, p0, 2);
                p1 += __shfl_xor_sync(0xffffffffu, p1, 1);
                p1 += __shfl_xor_sync(0xffffffffu, p1, 2);
                if (t == 0) {
                    red[lr0 * 5 + warpN] = p0;
                    red[(lr0 + 8) * 5 + warpN] = p1;
                }
            }
        }
        __syncthreads();   // curA reads done before next iter's cp.async overwrite
        if (ALPHA) {
            if (tid < BM) {
                int gr = rowBase + tid;
                if (gr < M) {
                    al0[gr] = red[tid * 5 + 0] + red[tid * 5 + 1];
                    al1[gr] = red[tid * 5 + 2] + red[tid * 5 + 3];
                }
            }
            __syncthreads();
        }
    }
}

// ---------------------------------------------------------------------------
// k_gemm_pf: round-7 register-prefetch persistent GEMM (L1 fused, 170 KB smem).
// ---------------------------------------------------------------------------
template <int K, int N, bool ALPHA, bool BIAS>
__global__ __launch_bounds__(256)
void k_gemm_pf(const float* __restrict__ X,
               const float* __restrict__ W0, const float* __restrict__ W1,
               const float* __restrict__ av0, const float* __restrict__ av1,
               const float* __restrict__ bias,
               float* __restrict__ Y0, float* __restrict__ Y1,
               float* __restrict__ al0, float* __restrict__ al1, int M) {
    constexpr int BM = 64;
    constexpr int KP = K + 4;
    constexpr int NP = N + 8;
    constexpr int WN = N / 4;
    constexpr int NT = WN / 8;
    constexpr int XF = BM * K / 1024;
    extern __shared__ float smf[];
    float* Wsm = smf;
    float* As  = smf + K * NP;
    float* red = As + BM * KP;

    const int tid = threadIdx.x;
    const int wid = tid >> 5;
    const int lane = tid & 31;
    const int warpM = wid >> 2;
    const int warpN = wid & 3;
    const int q = lane >> 2;
    const int t = lane & 3;

    for (int i = tid; i < K * N / 4; i += 256) {
        int k = i / (N / 4);
        int n4 = (i % (N / 4)) * 4;
        const float* src = (N == 256)
            ? ((n4 < 128) ? (W0 + (size_t)k * 128 + n4) : (W1 + (size_t)k * 128 + (n4 - 128)))
            : (W0 + (size_t)k * N + n4);
        float4 v = *(const float4*)src;
        v.x = f2tf32(v.x); v.y = f2tf32(v.y); v.z = f2tf32(v.z); v.w = f2tf32(v.w);
        *(float4*)(Wsm + k * NP + n4) = v;
    }

    const int ntiles = (M + BM - 1) / BM;
    int tile = blockIdx.x;
    float4 xr[XF];

    if (tile < ntiles) {
#pragma unroll
        for (int f = 0; f < XF; f++) {
            int i = tid + f * 256;
            int r = i / (K / 4);
            int c4 = (i % (K / 4)) * 4;
            int gr = tile * BM + r;
            xr[f] = (gr < M) ? *(const float4*)(X + (size_t)gr * K + c4)
                             : make_float4(0.f, 0.f, 0.f, 0.f);
        }
    }
    __syncthreads();

    for (; tile < ntiles; tile += gridDim.x) {
#pragma unroll
        for (int f = 0; f < XF; f++) {
            int i = tid + f * 256;
            int r = i / (K / 4);
            int c4 = (i % (K / 4)) * 4;
            float4 v = xr[f];
            v.x = f2tf32(v.x); v.y = f2tf32(v.y); v.z = f2tf32(v.z); v.w = f2tf32(v.w);
            *(float4*)(As + r * KP + c4) = v;
        }
        __syncthreads();

        int next = tile + gridDim.x;
        if (next < ntiles) {
#pragma unroll
            for (int f = 0; f < XF; f++) {
                int i = tid + f * 256;
                int r = i / (K / 4);
                int c4 = (i % (K / 4)) * 4;
                int gr = next * BM + r;
                xr[f] = (gr < M) ? *(const float4*)(X + (size_t)gr * K + c4)
                                 : make_float4(0.f, 0.f, 0.f, 0.f);
            }
        }

        float acc[2][NT][4];
#pragma unroll
        for (int mt = 0; mt < 2; mt++)
#pragma unroll
            for (int nt = 0; nt < NT; nt++)
#pragma unroll
                for (int j = 0; j < 4; j++) acc[mt][nt][j] = 0.f;

        const uint32_t* Au = (const uint32_t*)As;
        const uint32_t* Bu = (const uint32_t*)Wsm;

#pragma unroll
        for (int kk = 0; kk < K; kk += 8) {
            uint32_t a[2][4];
#pragma unroll
            for (int mt = 0; mt < 2; mt++) {
                int r0 = warpM * 32 + mt * 16 + q;
                a[mt][0] = Au[r0 * KP + kk + t];
                a[mt][1] = Au[(r0 + 8) * KP + kk + t];
                a[mt][2] = Au[r0 * KP + kk + 4 + t];
                a[mt][3] = Au[(r0 + 8) * KP + kk + 4 + t];
            }
            uint32_t b[NT][2];
#pragma unroll
            for (int nt = 0; nt < NT; nt++) {
                int nc = warpN * WN + nt * 8 + q;
                b[nt][0] = Bu[(kk + t) * NP + nc];
                b[nt][1] = Bu[(kk + 4 + t) * NP + nc];
            }
#pragma unroll
            for (int mt = 0; mt < 2; mt++)
#pragma unroll
                for (int nt = 0; nt < NT; nt++) {
                    asm("mma.sync.aligned.m16n8k8.row.col.f32.tf32.tf32.f32 "
                        "{%0,%1,%2,%3}, {%4,%5,%6,%7}, {%8,%9}, {%0,%1,%2,%3};"
                        : "+f"(acc[mt][nt][0]), "+f"(acc[mt][nt][1]),
                          "+f"(acc[mt][nt][2]), "+f"(acc[mt][nt][3])
                        : "r"(a[mt][0]), "r"(a[mt][1]), "r"(a[mt][2]), "r"(a[mt][3]),
                          "r"(b[nt][0]), "r"(b[nt][1]));
                }
        }

        const int rowBase = tile * BM;
#pragma unroll
        for (int mt = 0; mt < 2; mt++) {
            int lr0 = warpM * 32 + mt * 16 + q;
            int r0 = rowBase + lr0;
            float p0 = 0.f, p1 = 0.f;
#pragma unroll
            for (int nt = 0; nt < NT; nt++) {
                int cb = warpN * WN + nt * 8 + t * 2;
                float v0 = acc[mt][nt][0], v1 = acc[mt][nt][1];
                float v2 = acc[mt][nt][2], v3 = acc[mt][nt][3];
                if (BIAS) {
                    v0 += bias[cb]; v1 += bias[cb + 1];
                    v2 += bias[cb]; v3 += bias[cb + 1];
                }
                float* Yt;
                const float* avt;
                int cc;
                if (N == 256) {
                    bool hi = cb >= 128;
                    Yt = hi ? Y1 : Y0;
                    avt = hi ? av1 : av0;
                    cc = cb & 127;
                } else {
                    Yt = Y0; avt = av0; cc = cb;
                }
                constexpr int YSTR = (N == 256) ? 128 : N;
                if (r0 < M) *(float2*)(Yt + (size_t)r0 * YSTR + cc) = make_float2(v0, v1);
                if (r0 + 8 < M) *(float2*)(Yt + (size_t)(r0 + 8) * YSTR + cc) = make_float2(v2, v3);
                if (ALPHA) {
                    float a0 = avt[cc], a1 = avt[cc + 1];
                    p0 += v0 * a0 + v1 * a1;
                    p1 += v2 * a0 + v3 * a1;
                }
            }
            if (ALPHA) {
                p0 += __shfl_xor_sync(0xffffffffu, p0, 1);
                p0 += __shfl_xor_sync(0xffffffffu, p0, 2);
                p1 += __shfl_xor_sync(0xffffffffu, p1, 1);
                p1 += __shfl_xor_sync(0xffffffffu, p1, 2);
                if (t == 0) {
                    red[lr0 * 5 + warpN] = p0;
                    red[(lr0 + 8) * 5 + warpN] = p1;
                }
            }
        }
        __syncthreads();
        if (ALPHA) {
            if (tid < BM) {
                int gr = rowBase + tid;
                if (gr < M) {
                    al0[gr] = red[tid * 5 + 0] + red[tid * 5 + 1];
                    al1[gr] = red[tid * 5 + 2] + red[tid * 5 + 3];
                }
            }
            __syncthreads();
        }
    }
}

// ---------------------------------------------------------------------------
// Aggregation: one warp per target node; predicated always-4 loop.
// ---------------------------------------------------------------------------
__global__ __launch_bounds__(256)
void k_agg(const float4* __restrict__ tgt, const float4* __restrict__ src,
           const float* __restrict__ att,
           const int* __restrict__ off, const int* __restrict__ csr,
           float4* __restrict__ out, int n) {
    int w = (blockIdx.x * blockDim.x + threadIdx.x) >> 5;
    int lid = threadIdx.x & 31;
    if (w >= n) return;
    int beg = off[w];
    int end = off[w + 1];
    float4 acc = make_float4(0.f, 0.f, 0.f, 0.f);
    float den = 0.f;
    int e1 = end - 1;
    for (int j = beg; j < end; j += 4) {
        int i1 = j + 1 <= e1 ? j + 1 : e1;
        int i2 = j + 2 <= e1 ? j + 2 : e1;
        int i3 = j + 3 <= e1 ? j + 3 : e1;
        int s0 = csr[j], s1 = csr[i1], s2 = csr[i2], s3 = csr[i3];
        float a0 = att[j];
        float a1 = (j + 1 < end) ? att[i1] : 0.f;
        float a2 = (j + 2 < end) ? att[i2] : 0.f;
        float a3 = (j + 3 < end) ? att[i3] : 0.f;
        float4 v0 = src[(size_t)s0 * 32 + lid];
        float4 v1 = src[(size_t)s1 * 32 + lid];
        float4 v2 = src[(size_t)s2 * 32 + lid];
        float4 v3 = src[(size_t)s3 * 32 + lid];
        den += (a0 + a1) + (a2 + a3);
        acc.x += a0 * v0.x + a1 * v1.x + a2 * v2.x + a3 * v3.x;
        acc.y += a0 * v0.y + a1 * v1.y + a2 * v2.y + a3 * v3.y;
        acc.z += a0 * v0.z + a1 * v1.z + a2 * v2.z + a3 * v3.z;
        acc.w += a0 * v0.w + a1 * v1.w + a2 * v2.w + a3 * v3.w;
    }
    float inv = 1.0f / (den + EPSF);
    float4 tv = tgt[(size_t)w * 32 + lid];
    float4 r;
    r.x = fmaxf(tv.x + acc.x * inv, 0.f);
    r.y = fmaxf(tv.y + acc.y * inv, 0.f);
    r.z = fmaxf(tv.z + acc.z * inv, 0.f);
    r.w = fmaxf(tv.w + acc.w * inv, 0.f);
    out[(size_t)w * 32 + lid] = r;
}

// ---------------------------------------------------------------------------
// Host launcher
// ---------------------------------------------------------------------------
static inline float* symf(const void* sym) {
    void* p = nullptr;
    cudaGetSymbolAddress(&p, sym);
    return (float*)p;
}
static inline int* symi(const void* sym) {
    void* p = nullptr;
    cudaGetSymbolAddress(&p, sym);
    return (int*)p;
}

extern "C" void kernel_launch(void* const* d_in, const int* in_sizes, int n_in,
                              void* d_out, int out_size) {
    const float* x_user = (const float*)d_in[0];
    const float* x_spot = (const float*)d_in[1];
    const int*   e_us   = (const int*)d_in[2];
    const int*   e_su   = (const int*)d_in[3];
    const float* Ws_us0 = (const float*)d_in[4];
    const float* Wt_us0 = (const float*)d_in[5];
    const float* a_us0  = (const float*)d_in[6];
    const float* Ws_su0 = (const float*)d_in[7];
    const float* Wt_su0 = (const float*)d_in[8];
    const float* a_su0  = (const float*)d_in[9];
    const float* Ws_us1 = (const float*)d_in[10];
    const float* Wt_us1 = (const float*)d_in[11];
    const float* a_us1  = (const float*)d_in[12];
    const float* Ws_su1 = (const float*)d_in[13];
    const float* Wt_su1 = (const float*)d_in[14];
    const float* a_su1  = (const float*)d_in[15];
    const float* W_ou   = (const float*)d_in[16];
    const float* b_ou   = (const float*)d_in[17];
    const float* W_os   = (const float*)d_in[18];
    const float* b_os   = (const float*)d_in[19];

    float* out = (float*)d_out;
    float* xu_out = out;
    float* xs_out = out + (size_t)N_USER * HID;
    float* ou_out = xs_out + (size_t)N_SPOT * HID;
    float* os_out = ou_out + (size_t)N_USER * OUTC;

    float* srcA = symf(g_srcA); float* tgtA = symf(g_tgtA);
    float* srcB = symf(g_srcB); float* tgtB = symf(g_tgtB);
    float* hu = symf(g_hu);     float* hs = symf(g_hs);
    float* alsA = symf(g_alsA); float* altA = symf(g_altA);
    float* alsB = symf(g_alsB); float* altB = symf(g_altB);
    int* si2_us = symi(g_si2_us); int* si2_su = symi(g_si2_su);
    int* cnt_us = symi(g_cnt_us); int* off_us = symi(g_off_us); int* cur_us = symi(g_cur_us);
    int* cnt_su = symi(g_cnt_su); int* off_su = symi(g_off_su); int* cur_su = symi(g_cur_su);
    int* csr_us = symi(g_csr_us); int* csr_su = symi(g_csr_su);
    int* row_us = symi(g_row_us); int* row_su = symi(g_row_su);
    float* attb = symf(g_att);

    const int EB = (EDG + 255) / 256;
    const int GP = 296;
    const int GP1 = 148;
    const int AU = (N_USER * 32 + 255) / 256;
    const int AS = (N_SPOT * 32 + 255) / 256;

    const int SM_L0 = (64 * (256 + 8) + 2 * 64 * (64 + 4) + 64 * 5) * 4;     // ~104 KB
    const int SM_L1 = (128 * (256 + 8) + 64 * (128 + 4) + 64 * 5) * 4;       // ~170 KB
    const int SM_FN = (128 * (64 + 8) + 2 * 64 * (128 + 4) + 64 * 5) * 4;    // ~106 KB

    cudaFuncSetAttribute((const void*)k_gemm_db<64, 256, true, false>,
                         cudaFuncAttributeMaxDynamicSharedMemorySize, SM_L0);
    cudaFuncSetAttribute((const void*)k_gemm_pf<128, 256, true, false>,
                         cudaFuncAttributeMaxDynamicSharedMemorySize, SM_L1);
    cudaFuncSetAttribute((const void*)k_gemm_db<128, 64, false, true>,
                         cudaFuncAttributeMaxDynamicSharedMemorySize, SM_FN);

    // ---- prep; launch #5 = L0 DB GEMM (profiled) — same prefix as round 7 ----
    k_gather2<<<EB, 256>>>(e_us, si2_us, EDG);                               // 0
    k_gather2<<<EB, 256>>>(e_su, si2_su, EDG);                               // 1
    cudaMemsetAsync(cnt_us, 0, sizeof(int) * (N_SPOT + 1));                  // 2
    cudaMemsetAsync(cnt_su, 0, sizeof(int) * (N_USER + 1));                  // 3
    k_hist<<<EB, 256>>>(e_us + EDG, cnt_us, EDG);                            // 4
    // x_user -> [srcA | tgtB], alphas [alsA | altB]
    k_gemm_db<64, 256, true, false><<<GP, 256, SM_L0>>>(                     // 5
        x_user, Ws_us0, Wt_su0, a_us0, a_su0 + HID, nullptr,
        srcA, tgtB, alsA, altB, N_USER);
    k_hist<<<EB, 256>>>(e_su + EDG, cnt_su, EDG);
    k_scan<<<1, 1024>>>(cnt_us, off_us, cur_us, N_SPOT);
    k_scan<<<1, 1024>>>(cnt_su, off_su, cur_su, N_USER);
    k_scatter<<<EB, 256>>>(e_us + EDG, si2_us, cur_us, csr_us, row_us, EDG);
    k_scatter<<<EB, 256>>>(e_su + EDG, si2_su, cur_su, csr_su, row_su, EDG);
    // x_spot -> [srcB | tgtA], alphas [alsB | altA]
    k_gemm_db<64, 256, true, false><<<GP, 256, SM_L0>>>(
        x_spot, Ws_su0, Wt_us0, a_su0, a_us0 + HID, nullptr,
        srcB, tgtA, alsB, altA, N_SPOT);

    // ---- layer 0 aggregation ----
    k_att<<<EB, 256>>>(csr_us, row_us, alsA, altA, attb, EDG);
    k_agg<<<AS, 256>>>((const float4*)tgtA, (const float4*)srcA, attb,
                       off_us, csr_us, (float4*)hs, N_SPOT);
    k_att<<<EB, 256>>>(csr_su, row_su, alsB, altB, attb, EDG);
    k_agg<<<AU, 256>>>((const float4*)tgtB, (const float4*)srcB, attb,
                       off_su, csr_su, (float4*)hu, N_USER);

    // ---- layer 1 (K=128, fused, register-prefetch variant) ----
    k_gemm_pf<128, 256, true, false><<<GP1, 256, SM_L1>>>(
        hu, Ws_us1, Wt_su1, a_us1, a_su1 + HID, nullptr,
        srcA, tgtB, alsA, altB, N_USER);
    k_gemm_pf<128, 256, true, false><<<GP1, 256, SM_L1>>>(
        hs, Ws_su1, Wt_us1, a_su1, a_us1 + HID, nullptr,
        srcB, tgtA, alsB, altA, N_SPOT);
    k_att<<<EB, 256>>>(csr_us, row_us, alsA, altA, attb, EDG);
    k_agg<<<AS, 256>>>((const float4*)tgtA, (const float4*)srcA, attb,
                       off_us, csr_us, (float4*)xs_out, N_SPOT);
    k_att<<<EB, 256>>>(csr_su, row_su, alsB, altB, attb, EDG);
    k_agg<<<AU, 256>>>((const float4*)tgtB, (const float4*)srcB, attb,
                       off_su, csr_su, (float4*)xu_out, N_USER);

    // ---- final per-type linear (K=128, N=64, bias; DB variant) ----
    k_gemm_db<128, 64, false, true><<<GP, 256, SM_FN>>>(
        xu_out, W_ou, nullptr, nullptr, nullptr, b_ou,
        ou_out, nullptr, nullptr, nullptr, N_USER);
    k_gemm_db<128, 64, false, true><<<GP, 256, SM_FN>>>(
        xs_out, W_os, nullptr, nullptr, nullptr, b_os,
        os_out, nullptr, nullptr, nullptr, N_SPOT);
}

// round 10
// speedup vs baseline: 1.0821x; 1.0293x over previous
#include <cuda_runtime.h>
#include <cuda_bf16.h>
#include <cstdint>

#define N_USER 100000
#define N_SPOT 100000
#define F_IN   64
#define HID    128
#define OUTC   64
#define EDG    500000
#define LEAK   0.2f
#define EPSF   1e-6f

// ---------------------------------------------------------------------------
// Scratch (device globals; no allocation allowed)
// ---------------------------------------------------------------------------
__device__ float g_srcA[(size_t)N_USER * HID];
__device__ float g_tgtA[(size_t)N_SPOT * HID];
__device__ float g_srcB[(size_t)N_SPOT * HID];
__device__ float g_tgtB[(size_t)N_USER * HID];
__device__ float g_hu[(size_t)N_USER * HID];
__device__ float g_hs[(size_t)N_SPOT * HID];

__device__ float g_alsA[N_USER];
__device__ float g_altA[N_SPOT];
__device__ float g_alsB[N_SPOT];
__device__ float g_altB[N_USER];

__device__ int g_si2_us[EDG];
__device__ int g_si2_su[EDG];
__device__ int g_cnt_us[N_SPOT + 1];
__device__ int g_off_us[N_SPOT + 1];
__device__ int g_cur_us[N_SPOT + 1];
__device__ int g_cnt_su[N_USER + 1];
__device__ int g_off_su[N_USER + 1];
__device__ int g_cur_su[N_USER + 1];
__device__ int g_csr_us[EDG];
__device__ int g_csr_su[EDG];
__device__ int g_row_us[EDG];
__device__ int g_row_su[EDG];
__device__ float g_att[EDG];

__device__ __forceinline__ float f2tf32(float x) {
    float y;
    asm("cvt.rna.tf32.f32 %0, %1;" : "=f"(y) : "f"(x));
    return y;
}
__device__ __forceinline__ uint32_t smem_u32(const void* p) {
    uint32_t a;
    asm("{ .reg .u64 t; cvta.to.shared.u64 t, %1; cvt.u32.u64 %0, t; }" : "=r"(a) : "l"(p));
    return a;
}
__device__ __forceinline__ void cp_async16(void* dst, const void* src) {
    asm volatile("cp.async.ca.shared.global [%0], [%1], 16;"
                 :: "r"(smem_u32(dst)), "l"(src) : "memory");
}
__device__ __forceinline__ void cp_commit() {
    asm volatile("cp.async.commit_group;" ::: "memory");
}
template <int NG>
__device__ __forceinline__ void cp_wait() {
    asm volatile("cp.async.wait_group %0;" :: "n"(NG) : "memory");
}

// ---------------------------------------------------------------------------
// Edge prep kernels
// ---------------------------------------------------------------------------
__global__ void k_gather2(const int* __restrict__ si, int* __restrict__ s2, int E) {
    int e = blockIdx.x * blockDim.x + threadIdx.x;
    if (e < E) {
        int a = si[e];
        s2[e] = si[a];
    }
}

__global__ void k_hist(const int* __restrict__ ti, int* __restrict__ cnt, int E) {
    int e = blockIdx.x * blockDim.x + threadIdx.x;
    if (e < E) atomicAdd(&cnt[ti[e]], 1);
}

__global__ void k_scan(const int* __restrict__ cnt, int* __restrict__ off,
                       int* __restrict__ cur, int n) {
    __shared__ int s[1024];
    int tid = threadIdx.x;
    int chunk = (n + 1023) / 1024;
    int beg = tid * chunk;
    int end = beg + chunk; if (end > n) end = n; if (beg > n) beg = n;
    int sum = 0;
    for (int i = beg; i < end; i++) sum += cnt[i];
    s[tid] = sum;
    __syncthreads();
    for (int d = 1; d < 1024; d <<= 1) {
        int v = 0;
        if (tid >= d) v = s[tid - d];
        __syncthreads();
        s[tid] += v;
        __syncthreads();
    }
    int run = s[tid] - sum;
    for (int i = beg; i < end; i++) {
        off[i] = run; cur[i] = run;
        run += cnt[i];
    }
    if (tid == 1023) off[n] = s[1023];
}

__global__ void k_scatter(const int* __restrict__ ti, const int* __restrict__ s2,
                          int* __restrict__ cur, int* __restrict__ csr,
                          int* __restrict__ rowOf, int E) {
    int e = blockIdx.x * blockDim.x + threadIdx.x;
    if (e < E) {
        int t = ti[e];
        int p = atomicAdd(&cur[t], 1);
        csr[p] = s2[e];
        rowOf[p] = t;
    }
}

__global__ void k_att(const int* __restrict__ csr, const int* __restrict__ rowOf,
                      const float* __restrict__ alpha_s, const float* __restrict__ alpha_t,
                      float* __restrict__ att, int E) {
    int j = blockIdx.x * blockDim.x + threadIdx.x;
    if (j < E) {
        float l = alpha_s[csr[j]] + alpha_t[rowOf[j]];
        l = (l > 0.f) ? l : LEAK * l;
        att[j] = __expf(l);
    }
}

// ---------------------------------------------------------------------------
// k_gemm_db: persistent, cp.async double-buffered A (in-smem tf32 convert),
//            W resident, 2 CTAs/SM. Used for L0 (64,256) and FN (128,64).
// ---------------------------------------------------------------------------
template <int K, int N, bool ALPHA, bool BIAS>
__global__ __launch_bounds__(256, 2)
void k_gemm_db(const float* __restrict__ X,
               const float* __restrict__ W0, const float* __restrict__ W1,
               const float* __restrict__ av0, const float* __restrict__ av1,
               const float* __restrict__ bias,
               float* __restrict__ Y0, float* __restrict__ Y1,
               float* __restrict__ al0, float* __restrict__ al1, int M) {
    constexpr int BM = 64;
    constexpr int KP = K + 4;
    constexpr int NP = N + 8;
    constexpr int WN = N / 4;
    constexpr int NT = WN / 8;
    constexpr int XF = BM * K / 1024;
    extern __shared__ float smf[];
    float* Wsm = smf;                     // [K][NP]
    float* A0  = smf + K * NP;            // [BM][KP] x2
    float* A1  = A0 + BM * KP;
    float* red = A1 + BM * KP;            // [BM][5]

    const int tid = threadIdx.x;
    const int wid = tid >> 5;
    const int lane = tid & 31;
    const int warpM = wid >> 2;
    const int warpN = wid & 3;
    const int q = lane >> 2;
    const int t = lane & 3;

    for (int i = tid; i < K * N / 4; i += 256) {
        int k = i / (N / 4);
        int n4 = (i % (N / 4)) * 4;
        const float* src = (N == 256)
            ? ((n4 < 128) ? (W0 + (size_t)k * 128 + n4) : (W1 + (size_t)k * 128 + (n4 - 128)))
            : (W0 + (size_t)k * N + n4);
        float4 v = *(const float4*)src;
        v.x = f2tf32(v.x); v.y = f2tf32(v.y); v.z = f2tf32(v.z); v.w = f2tf32(v.w);
        *(float4*)(Wsm + k * NP + n4) = v;
    }

    const int ntiles = (M + BM - 1) / BM;

    if ((int)blockIdx.x < ntiles) {
#pragma unroll
        for (int f = 0; f < XF; f++) {
            int i = tid + f * 256;
            int r = i / (K / 4);
            int c4 = (i % (K / 4)) * 4;
            int gr = blockIdx.x * BM + r;
            if (gr >= M) gr = M - 1;
            cp_async16(A0 + r * KP + c4, X + (size_t)gr * K + c4);
        }
    }
    cp_commit();

    int it = 0;
    for (int tile = blockIdx.x; tile < ntiles; tile += gridDim.x, it++) {
        float* curA = (it & 1) ? A1 : A0;
        float* nxtA = (it & 1) ? A0 : A1;

        int next = tile + gridDim.x;
        if (next < ntiles) {
#pragma unroll
            for (int f = 0; f < XF; f++) {
                int i = tid + f * 256;
                int r = i / (K / 4);
                int c4 = (i % (K / 4)) * 4;
                int gr = next * BM + r;
                if (gr >= M) gr = M - 1;
                cp_async16(nxtA + r * KP + c4, X + (size_t)gr * K + c4);
            }
        }
        cp_commit();
        cp_wait<1>();
#pragma unroll
        for (int f = 0; f < XF; f++) {
            int i = tid + f * 256;
            int r = i / (K / 4);
            int c4 = (i % (K / 4)) * 4;
            float4 v = *(const float4*)(curA + r * KP + c4);
            v.x = f2tf32(v.x); v.y = f2tf32(v.y); v.z = f2tf32(v.z); v.w = f2tf32(v.w);
            *(float4*)(curA + r * KP + c4) = v;
        }
        __syncthreads();

        float acc[2][NT][4];
#pragma unroll
        for (int mt = 0; mt < 2; mt++)
#pragma unroll
            for (int nt = 0; nt < NT; nt++)
#pragma unroll
                for (int j = 0; j < 4; j++) acc[mt][nt][j] = 0.f;

        const uint32_t* Au = (const uint32_t*)curA;
        const uint32_t* Bu = (const uint32_t*)Wsm;

#pragma unroll
        for (int kk = 0; kk < K; kk += 8) {
            uint32_t a[2][4];
#pragma unroll
            for (int mt = 0; mt < 2; mt++) {
                int r0 = warpM * 32 + mt * 16 + q;
                a[mt][0] = Au[r0 * KP + kk + t];
                a[mt][1] = Au[(r0 + 8) * KP + kk + t];
                a[mt][2] = Au[r0 * KP + kk + 4 + t];
                a[mt][3] = Au[(r0 + 8) * KP + kk + 4 + t];
            }
            uint32_t b[NT][2];
#pragma unroll
            for (int nt = 0; nt < NT; nt++) {
                int nc = warpN * WN + nt * 8 + q;
                b[nt][0] = Bu[(kk + t) * NP + nc];
                b[nt][1] = Bu[(kk + 4 + t) * NP + nc];
            }
#pragma unroll
            for (int mt = 0; mt < 2; mt++)
#pragma unroll
                for (int nt = 0; nt < NT; nt++) {
                    asm("mma.sync.aligned.m16n8k8.row.col.f32.tf32.tf32.f32 "
                        "{%0,%1,%2,%3}, {%4,%5,%6,%7}, {%8,%9}, {%0,%1,%2,%3};"
                        : "+f"(acc[mt][nt][0]), "+f"(acc[mt][nt][1]),
                          "+f"(acc[mt][nt][2]), "+f"(acc[mt][nt][3])
                        : "r"(a[mt][0]), "r"(a[mt][1]), "r"(a[mt][2]), "r"(a[mt][3]),
                          "r"(b[nt][0]), "r"(b[nt][1]));
                }
        }

        const int rowBase = tile * BM;
#pragma unroll
        for (int mt = 0; mt < 2; mt++) {
            int lr0 = warpM * 32 + mt * 16 + q;
            int r0 = rowBase + lr0;
            float p0 = 0.f, p1 = 0.f;
#pragma unroll
            for (int nt = 0; nt < NT; nt++) {
                int cb = warpN * WN + nt * 8 + t * 2;
                float v0 = acc[mt][nt][0], v1 = acc[mt][nt][1];
                float v2 = acc[mt][nt][2], v3 = acc[mt][nt][3];
                if (BIAS) {
                    v0 += bias[cb]; v1 += bias[cb + 1];
                    v2 += bias[cb]; v3 += bias[cb + 1];
                }
                float* Yt;
                const float* avt;
                int cc;
                if (N == 256) {
                    bool hi = cb >= 128;
                    Yt = hi ? Y1 : Y0;
                    avt = hi ? av1 : av0;
                    cc = cb & 127;
                } else {
                    Yt = Y0; avt = av0; cc = cb;
                }
                constexpr int YSTR = (N == 256) ? 128 : N;
                if (BIAS) {
                    // final outputs: never re-read -> streaming stores
                    if (r0 < M) __stcs((float2*)(Yt + (size_t)r0 * YSTR + cc), make_float2(v0, v1));
                    if (r0 + 8 < M) __stcs((float2*)(Yt + (size_t)(r0 + 8) * YSTR + cc), make_float2(v2, v3));
                } else {
                    if (r0 < M) *(float2*)(Yt + (size_t)r0 * YSTR + cc) = make_float2(v0, v1);
                    if (r0 + 8 < M) *(float2*)(Yt + (size_t)(r0 + 8) * YSTR + cc) = make_float2(v2, v3);
                }
                if (ALPHA) {
                    float a0 = avt[cc], a1 = avt[cc + 1];
                    p0 += v0 * a0 + v1 * a1;
                    p1 += v2 * a0 + v3 * a1;
                }
            }
            if (ALPHA) {
                p0 += __shfl_xor_sync(0xffffffffu, p0, 1);
                p0 += __shfl_xor_sync(0xffffffffu, p0, 2);
                p1 += __shfl_xor_sync(0xffffffffu, p1, 1);
                p1 += __shfl_xor_sync(0xffffffffu, p1, 2);
                if (t == 0) {
                    red[lr0 * 5 + warpN] = p0;
                    red[(lr0 + 8) * 5 + warpN] = p1;
                }
            }
        }
        __syncthreads();
        if (ALPHA) {
            if (tid < BM) {
                int gr = rowBase + tid;
                if (gr < M) {
                    al0[gr] = red[tid * 5 + 0] + red[tid * 5 + 1];
                    al1[gr] = red[tid * 5 + 2] + red[tid * 5 + 3];
                }
            }
            __syncthreads();
        }
    }
}

// ---------------------------------------------------------------------------
// k_gemm_pf: register-prefetch persistent GEMM (L1 fused, 170 KB smem).
// ---------------------------------------------------------------------------
template <int K, int N, bool ALPHA, bool BIAS>
__global__ __launch_bounds__(256)
void k_gemm_pf(const float* __restrict__ X,
               const float* __restrict__ W0, const float* __restrict__ W1,
               const float* __restrict__ av0, const float* __restrict__ av1,
               const float* __restrict__ bias,
               float* __restrict__ Y0, float* __restrict__ Y1,
               float* __restrict__ al0, float* __restrict__ al1, int M) {
    constexpr int BM = 64;
    constexpr int KP = K + 4;
    constexpr int NP = N + 8;
    constexpr int WN = N / 4;
    constexpr int NT = WN / 8;
    constexpr int XF = BM * K / 1024;
    extern __shared__ float smf[];
    float* Wsm = smf;
    float* As  = smf + K * NP;
    float* red = As + BM * KP;

    const int tid = threadIdx.x;
    const int wid = tid >> 5;
    const int lane = tid & 31;
    const int warpM = wid >> 2;
    const int warpN = wid & 3;
    const int q = lane >> 2;
    const int t = lane & 3;

    for (int i = tid; i < K * N / 4; i += 256) {
        int k = i / (N / 4);
        int n4 = (i % (N / 4)) * 4;
        const float* src = (N == 256)
            ? ((n4 < 128) ? (W0 + (size_t)k * 128 + n4) : (W1 + (size_t)k * 128 + (n4 - 128)))
            : (W0 + (size_t)k * N + n4);
        float4 v = *(const float4*)src;
        v.x = f2tf32(v.x); v.y = f2tf32(v.y); v.z = f2tf32(v.z); v.w = f2tf32(v.w);
        *(float4*)(Wsm + k * NP + n4) = v;
    }

    const int ntiles = (M + BM - 1) / BM;
    int tile = blockIdx.x;
    float4 xr[XF];

    if (tile < ntiles) {
#pragma unroll
        for (int f = 0; f < XF; f++) {
            int i = tid + f * 256;
            int r = i / (K / 4);
            int c4 = (i % (K / 4)) * 4;
            int gr = tile * BM + r;
            xr[f] = (gr < M) ? *(const float4*)(X + (size_t)gr * K + c4)
                             : make_float4(0.f, 0.f, 0.f, 0.f);
        }
    }
    __syncthreads();

    for (; tile < ntiles; tile += gridDim.x) {
#pragma unroll
        for (int f = 0; f < XF; f++) {
            int i = tid + f * 256;
            int r = i / (K / 4);
            int c4 = (i % (K / 4)) * 4;
            float4 v = xr[f];
            v.x = f2tf32(v.x); v.y = f2tf32(v.y); v.z = f2tf32(v.z); v.w = f2tf32(v.w);
            *(float4*)(As + r * KP + c4) = v;
        }
        __syncthreads();

        int next = tile + gridDim.x;
        if (next < ntiles) {
#pragma unroll
            for (int f = 0; f < XF; f++) {
                int i = tid + f * 256;
                int r = i / (K / 4);
                int c4 = (i % (K / 4)) * 4;
                int gr = next * BM + r;
                xr[f] = (gr < M) ? *(const float4*)(X + (size_t)gr * K + c4)
                                 : make_float4(0.f, 0.f, 0.f, 0.f);
            }
        }

        float acc[2][NT][4];
#pragma unroll
        for (int mt = 0; mt < 2; mt++)
#pragma unroll
            for (int nt = 0; nt < NT; nt++)
#pragma unroll
                for (int j = 0; j < 4; j++) acc[mt][nt][j] = 0.f;

        const uint32_t* Au = (const uint32_t*)As;
        const uint32_t* Bu = (const uint32_t*)Wsm;

#pragma unroll
        for (int kk = 0; kk < K; kk += 8) {
            uint32_t a[2][4];
#pragma unroll
            for (int mt = 0; mt < 2; mt++) {
                int r0 = warpM * 32 + mt * 16 + q;
                a[mt][0] = Au[r0 * KP + kk + t];
                a[mt][1] = Au[(r0 + 8) * KP + kk + t];
                a[mt][2] = Au[r0 * KP + kk + 4 + t];
                a[mt][3] = Au[(r0 + 8) * KP + kk + 4 + t];
            }
            uint32_t b[NT][2];
#pragma unroll
            for (int nt = 0; nt < NT; nt++) {
                int nc = warpN * WN + nt * 8 + q;
                b[nt][0] = Bu[(kk + t) * NP + nc];
                b[nt][1] = Bu[(kk + 4 + t) * NP + nc];
            }
#pragma unroll
            for (int mt = 0; mt < 2; mt++)
#pragma unroll
                for (int nt = 0; nt < NT; nt++) {
                    asm("mma.sync.aligned.m16n8k8.row.col.f32.tf32.tf32.f32 "
                        "{%0,%1,%2,%3}, {%4,%5,%6,%7}, {%8,%9}, {%0,%1,%2,%3};"
                        : "+f"(acc[mt][nt][0]), "+f"(acc[mt][nt][1]),
                          "+f"(acc[mt][nt][2]), "+f"(acc[mt][nt][3])
                        : "r"(a[mt][0]), "r"(a[mt][1]), "r"(a[mt][2]), "r"(a[mt][3]),
                          "r"(b[nt][0]), "r"(b[nt][1]));
                }
        }

        const int rowBase = tile * BM;
#pragma unroll
        for (int mt = 0; mt < 2; mt++) {
            int lr0 = warpM * 32 + mt * 16 + q;
            int r0 = rowBase + lr0;
            float p0 = 0.f, p1 = 0.f;
#pragma unroll
            for (int nt = 0; nt < NT; nt++) {
                int cb = warpN * WN + nt * 8 + t * 2;
                float v0 = acc[mt][nt][0], v1 = acc[mt][nt][1];
                float v2 = acc[mt][nt][2], v3 = acc[mt][nt][3];
                if (BIAS) {
                    v0 += bias[cb]; v1 += bias[cb + 1];
                    v2 += bias[cb]; v3 += bias[cb + 1];
                }
                float* Yt;
                const float* avt;
                int cc;
                if (N == 256) {
                    bool hi = cb >= 128;
                    Yt = hi ? Y1 : Y0;
                    avt = hi ? av1 : av0;
                    cc = cb & 127;
                } else {
                    Yt = Y0; avt = av0; cc = cb;
                }
                constexpr int YSTR = (N == 256) ? 128 : N;
                if (r0 < M) *(float2*)(Yt + (size_t)r0 * YSTR + cc) = make_float2(v0, v1);
                if (r0 + 8 < M) *(float2*)(Yt + (size_t)(r0 + 8) * YSTR + cc) = make_float2(v2, v3);
                if (ALPHA) {
                    float a0 = avt[cc], a1 = avt[cc + 1];
                    p0 += v0 * a0 + v1 * a1;
                    p1 += v2 * a0 + v3 * a1;
                }
            }
            if (ALPHA) {
                p0 += __shfl_xor_sync(0xffffffffu, p0, 1);
                p0 += __shfl_xor_sync(0xffffffffu, p0, 2);
                p1 += __shfl_xor_sync(0xffffffffu, p1, 1);
                p1 += __shfl_xor_sync(0xffffffffu, p1, 2);
                if (t == 0) {
                    red[lr0 * 5 + warpN] = p0;
                    red[(lr0 + 8) * 5 + warpN] = p1;
                }
            }
        }
        __syncthreads();
        if (ALPHA) {
            if (tid < BM) {
                int gr = rowBase + tid;
                if (gr < M) {
                    al0[gr] = red[tid * 5 + 0] + red[tid * 5 + 1];
                    al1[gr] = red[tid * 5 + 2] + red[tid * 5 + 3];
                }
            }
            __syncthreads();
        }
    }
}

// ---------------------------------------------------------------------------
// Aggregation: one warp per target node; 4+2+1 tails (only real loads);
// streaming hints on tgt/out so the gathered src table stays L2-resident.
// ---------------------------------------------------------------------------
__global__ __launch_bounds__(256)
void k_agg(const float4* __restrict__ tgt, const float4* __restrict__ src,
           const float* __restrict__ att,
           const int* __restrict__ off, const int* __restrict__ csr,
           float4* __restrict__ out, int n) {
    int w = (blockIdx.x * blockDim.x + threadIdx.x) >> 5;
    int lid = threadIdx.x & 31;
    if (w >= n) return;
    int beg = off[w];
    int end = off[w + 1];
    float4 acc = make_float4(0.f, 0.f, 0.f, 0.f);
    float den = 0.f;
    int j = beg;
    for (; j + 3 < end; j += 4) {
        int s0 = csr[j + 0], s1 = csr[j + 1], s2 = csr[j + 2], s3 = csr[j + 3];
        float a0 = att[j + 0], a1 = att[j + 1], a2 = att[j + 2], a3 = att[j + 3];
        float4 v0 = src[(size_t)s0 * 32 + lid];
        float4 v1 = src[(size_t)s1 * 32 + lid];
        float4 v2 = src[(size_t)s2 * 32 + lid];
        float4 v3 = src[(size_t)s3 * 32 + lid];
        den += (a0 + a1) + (a2 + a3);
        acc.x += a0 * v0.x + a1 * v1.x + a2 * v2.x + a3 * v3.x;
        acc.y += a0 * v0.y + a1 * v1.y + a2 * v2.y + a3 * v3.y;
        acc.z += a0 * v0.z + a1 * v1.z + a2 * v2.z + a3 * v3.z;
        acc.w += a0 * v0.w + a1 * v1.w + a2 * v2.w + a3 * v3.w;
    }
    if (j + 1 < end) {
        int s0 = csr[j + 0], s1 = csr[j + 1];
        float a0 = att[j + 0], a1 = att[j + 1];
        float4 v0 = src[(size_t)s0 * 32 + lid];
        float4 v1 = src[(size_t)s1 * 32 + lid];
        den += a0 + a1;
        acc.x += a0 * v0.x + a1 * v1.x;
        acc.y += a0 * v0.y + a1 * v1.y;
        acc.z += a0 * v0.z + a1 * v1.z;
        acc.w += a0 * v0.w + a1 * v1.w;
        j += 2;
    }
    if (j < end) {
        int s0 = csr[j];
        float a0 = att[j];
        float4 v0 = src[(size_t)s0 * 32 + lid];
        den += a0;
        acc.x += a0 * v0.x; acc.y += a0 * v0.y;
        acc.z += a0 * v0.z; acc.w += a0 * v0.w;
    }
    float inv = 1.0f / (den + EPSF);
    float4 tv = __ldcs(&tgt[(size_t)w * 32 + lid]);   // streaming read
    float4 r;
    r.x = fmaxf(tv.x + acc.x * inv, 0.f);
    r.y = fmaxf(tv.y + acc.y * inv, 0.f);
    r.z = fmaxf(tv.z + acc.z * inv, 0.f);
    r.w = fmaxf(tv.w + acc.w * inv, 0.f);
    __stcs(&out[(size_t)w * 32 + lid], r);            // streaming write
}

// ---------------------------------------------------------------------------
// Host launcher
// ---------------------------------------------------------------------------
static inline float* symf(const void* sym) {
    void* p = nullptr;
    cudaGetSymbolAddress(&p, sym);
    return (float*)p;
}
static inline int* symi(const void* sym) {
    void* p = nullptr;
    cudaGetSymbolAddress(&p, sym);
    return (int*)p;
}

extern "C" void kernel_launch(void* const* d_in, const int* in_sizes, int n_in,
                              void* d_out, int out_size) {
    const float* x_user = (const float*)d_in[0];
    const float* x_spot = (const float*)d_in[1];
    const int*   e_us   = (const int*)d_in[2];
    const int*   e_su   = (const int*)d_in[3];
    const float* Ws_us0 = (const float*)d_in[4];
    const float* Wt_us0 = (const float*)d_in[5];
    const float* a_us0  = (const float*)d_in[6];
    const float* Ws_su0 = (const float*)d_in[7];
    const float* Wt_su0 = (const float*)d_in[8];
    const float* a_su0  = (const float*)d_in[9];
    const float* Ws_us1 = (const float*)d_in[10];
    const float* Wt_us1 = (const float*)d_in[11];
    const float* a_us1  = (const float*)d_in[12];
    const float* Ws_su1 = (const float*)d_in[13];
    const float* Wt_su1 = (const float*)d_in[14];
    const float* a_su1  = (const float*)d_in[15];
    const float* W_ou   = (const float*)d_in[16];
    const float* b_ou   = (const float*)d_in[17];
    const float* W_os   = (const float*)d_in[18];
    const float* b_os   = (const float*)d_in[19];

    float* out = (float*)d_out;
    float* xu_out = out;
    float* xs_out = out + (size_t)N_USER * HID;
    float* ou_out = xs_out + (size_t)N_SPOT * HID;
    float* os_out = ou_out + (size_t)N_USER * OUTC;

    float* srcA = symf(g_srcA); float* tgtA = symf(g_tgtA);
    float* srcB = symf(g_srcB); float* tgtB = symf(g_tgtB);
    float* hu = symf(g_hu);     float* hs = symf(g_hs);
    float* alsA = symf(g_alsA); float* altA = symf(g_altA);
    float* alsB = symf(g_alsB); float* altB = symf(g_altB);
    int* si2_us = symi(g_si2_us); int* si2_su = symi(g_si2_su);
    int* cnt_us = symi(g_cnt_us); int* off_us = symi(g_off_us); int* cur_us = symi(g_cur_us);
    int* cnt_su = symi(g_cnt_su); int* off_su = symi(g_off_su); int* cur_su = symi(g_cur_su);
    int* csr_us = symi(g_csr_us); int* csr_su = symi(g_csr_su);
    int* row_us = symi(g_row_us); int* row_su = symi(g_row_su);
    float* attb = symf(g_att);

    const int EB = (EDG + 255) / 256;
    const int GP = 296;
    const int GP1 = 148;
    const int AU = (N_USER * 32 + 255) / 256;
    const int AS = (N_SPOT * 32 + 255) / 256;

    const int SM_L0 = (64 * (256 + 8) + 2 * 64 * (64 + 4) + 64 * 5) * 4;     // ~104 KB
    const int SM_L1 = (128 * (256 + 8) + 64 * (128 + 4) + 64 * 5) * 4;       // ~170 KB
    const int SM_FN = (128 * (64 + 8) + 2 * 64 * (128 + 4) + 64 * 5) * 4;    // ~106 KB

    cudaFuncSetAttribute((const void*)k_gemm_db<64, 256, true, false>,
                         cudaFuncAttributeMaxDynamicSharedMemorySize, SM_L0);
    cudaFuncSetAttribute((const void*)k_gemm_pf<128, 256, true, false>,
                         cudaFuncAttributeMaxDynamicSharedMemorySize, SM_L1);
    cudaFuncSetAttribute((const void*)k_gemm_db<128, 64, false, true>,
                         cudaFuncAttributeMaxDynamicSharedMemorySize, SM_FN);

    // ---- prep; launch #5 = L0 DB GEMM (profiled) ----
    k_gather2<<<EB, 256>>>(e_us, si2_us, EDG);                               // 0
    k_gather2<<<EB, 256>>>(e_su, si2_su, EDG);                               // 1
    cudaMemsetAsync(cnt_us, 0, sizeof(int) * (N_SPOT + 1));                  // 2
    cudaMemsetAsync(cnt_su, 0, sizeof(int) * (N_USER + 1));                  // 3
    k_hist<<<EB, 256>>>(e_us + EDG, cnt_us, EDG);                            // 4
    k_gemm_db<64, 256, true, false><<<GP, 256, SM_L0>>>(                     // 5
        x_user, Ws_us0, Wt_su0, a_us0, a_su0 + HID, nullptr,
        srcA, tgtB, alsA, altB, N_USER);
    k_hist<<<EB, 256>>>(e_su + EDG, cnt_su, EDG);
    k_scan<<<1, 1024>>>(cnt_us, off_us, cur_us, N_SPOT);
    k_scan<<<1, 1024>>>(cnt_su, off_su, cur_su, N_USER);
    k_scatter<<<EB, 256>>>(e_us + EDG, si2_us, cur_us, csr_us, row_us, EDG);
    k_scatter<<<EB, 256>>>(e_su + EDG, si2_su, cur_su, csr_su, row_su, EDG);
    k_gemm_db<64, 256, true, false><<<GP, 256, SM_L0>>>(
        x_spot, Ws_su0, Wt_us0, a_su0, a_us0 + HID, nullptr,
        srcB, tgtA, alsB, altA, N_SPOT);

    // ---- layer 0 aggregation ----
    k_att<<<EB, 256>>>(csr_us, row_us, alsA, altA, attb, EDG);
    k_agg<<<AS, 256>>>((const float4*)tgtA, (const float4*)srcA, attb,
                       off_us, csr_us, (float4*)hs, N_SPOT);
    k_att<<<EB, 256>>>(csr_su, row_su, alsB, altB, attb, EDG);
    k_agg<<<AU, 256>>>((const float4*)tgtB, (const float4*)srcB, attb,
                       off_su, csr_su, (float4*)hu, N_USER);

    // ---- layer 1 (K=128, fused, register-prefetch variant) ----
    k_gemm_pf<128, 256, true, false><<<GP1, 256, SM_L1>>>(
        hu, Ws_us1, Wt_su1, a_us1, a_su1 + HID, nullptr,
        srcA, tgtB, alsA, altB, N_USER);
    k_gemm_pf<128, 256, true, false><<<GP1, 256, SM_L1>>>(
        hs, Ws_su1, Wt_us1, a_su1, a_us1 + HID, nullptr,
        srcB, tgtA, alsB, altA, N_SPOT);
    k_att<<<EB, 256>>>(csr_us, row_us, alsA, altA, attb, EDG);
    k_agg<<<AS, 256>>>((const float4*)tgtA, (const float4*)srcA, attb,
                       off_us, csr_us, (float4*)xs_out, N_SPOT);
    k_att<<<EB, 256>>>(csr_su, row_su, alsB, altB, attb, EDG);
    k_agg<<<AU, 256>>>((const float4*)tgtB, (const float4*)srcB, attb,
                       off_su, csr_su, (float4*)xu_out, N_USER);

    // ---- final per-type linear (K=128, N=64, bias; DB variant) ----
    k_gemm_db<128, 64, false, true><<<GP, 256, SM_FN>>>(
        xu_out, W_ou, nullptr, nullptr, nullptr, b_ou,
        ou_out, nullptr, nullptr, nullptr, N_USER);
    k_gemm_db<128, 64, false, true><<<GP, 256, SM_FN>>>(
        xs_out, W_os, nullptr, nullptr, nullptr, b_os,
        os_out, nullptr, nullptr, nullptr, N_SPOT);
}